// round 16
// baseline (speedup 1.0000x reference)
#include <cuda_runtime.h>
#include <math.h>
#include <stdint.h>

#define NB    32
#define NTIN  512
#define NE    576
#define NT    400
#define NMELD 80
#define NPRE  256
#define NAR   1024
#define NDR   1024
#define NAD   128

#define GATE_OFF  (NB*NMELD*NT)
#define ALIGN_OFF (GATE_OFF + NB*NT)

#define NTHR 512

// ---------------- static device scratch ----------------
__device__ float g_WAT[(size_t)3*1856*1024 + 16384];  // att weights [g][k][u] (+pad for prefetch overread)
__device__ float g_WDT[(size_t)4*2624*1024 + 16384];  // dec weights [g][k][u], k=[ah|dh|ctx] (+pad)
__device__ float g_X1 [(size_t)NT*NB*NPRE];           // [t][b][k]
__device__ float g_X2T[(size_t)NT*NPRE*NB];           // [t][k][b]
__device__ float g_PMEM[(size_t)NB*NTIN*NAD];         // [b][s][d]
__device__ float g_LOC [(size_t)NB*NTIN*NAD];         // [b][s][d]
__device__ float g_CW2T[64*128];                      // [ck][d]
__device__ float g_locb2[128];
__device__ float g_AC[2][NAR*NB];                     // [u][b], ah == ac
__device__ float g_ACT[NB*NAR];                       // [b][u] transposed ah copy
__device__ float g_DC[NDR*NB];                        // [u][b]
__device__ float g_DH[(size_t)(NT+1)*NDR*NB];         // [t][u][b]
__device__ float g_CTX[(size_t)(NT+1)*NE*NB];         // [t][e][b]
__device__ float g_AW [NB*NTIN];
__device__ float g_AWC[NB*NTIN];
__device__ float g_GPA[(size_t)18*3*1024*32];         // att partials [seg][g][u][b]
__device__ float g_GPD[(size_t)19*4*1024*32];         // dec partials [slot][g][u][b]

__device__ unsigned g_bar_arrive;
__device__ volatile unsigned g_bar_flag;

__device__ __forceinline__ float sigf(float x){ return 1.f/(1.f+expf(-x)); }
__device__ __forceinline__ float ftanh(float x){
    x = fminf(8.f, fmaxf(-8.f, x));
    float e = __expf(2.f*x);
    return (e-1.f)/(e+1.f);
}

__device__ __forceinline__ void gsync(unsigned &gen)
{
    __syncthreads();
    gen++;
    if (threadIdx.x == 0){
        __threadfence();
        unsigned a = atomicAdd(&g_bar_arrive, 1u);
        if (a == gridDim.x - 1){
            g_bar_arrive = 0;
            __threadfence();
            g_bar_flag = gen;
        } else {
            while (g_bar_flag < gen) { __nanosleep(40); }
        }
        __threadfence();
    }
    __syncthreads();
}

__device__ __forceinline__ void copy4(float* dst, const float* src, int nfl, int tid)
{
    const float4* s4 = (const float4*)src;
    float4* d4 = (float4*)dst;
    int n4 = nfl >> 2;
    for (int i = tid; i < n4; i += NTHR) d4[i] = s4[i];
}

__device__ __forceinline__ void zpad(float* sx, int klen, int klenp, int tid)
{
    for (int i = klen*32 + tid; i < klenp*32; i += NTHR) sx[i] = 0.f;
}

#define FMA2(acc, a, b) asm("fma.rn.f32x2 %0, %1, %2, %0;" : "+l"(acc) : "l"(a), "l"(b))

// coalesced-weight GEMV: lane owns unit u, 32 b in 16 packed f32x2 accs.
// Software-pipelined: 4+4 double-buffered weight prefetch (same 8 w regs),
// so every weight load issues ~1 half-chunk of FMA2s before first use.
// klen8 multiple of 8; sx zero-padded; wcol padded for benign overread.
__device__ __forceinline__ void gemv2(const float* __restrict__ wcol,
                                      const float* __restrict__ sx, int klen8,
                                      unsigned long long* acc)
{
    float wa[4], wb[4];
#pragma unroll
    for (int i=0;i<4;i++) wa[i] = __ldg(wcol + (size_t)i*1024);
    for (int k0 = 0; k0 < klen8; k0 += 8){
        // load second half of current chunk
#pragma unroll
        for (int i=0;i<4;i++) wb[i] = __ldg(wcol + (size_t)(k0+4+i)*1024);
        // compute first half
#pragma unroll
        for (int i=0;i<4;i++){
            unsigned long long wp;
            asm("mov.b64 %0, {%1, %1};" : "=l"(wp) : "r"(__float_as_uint(wa[i])));
            const ulonglong2* xr = (const ulonglong2*)(sx + (size_t)(k0+i)*32);
#pragma unroll
            for (int q = 0; q < 8; q++){
                ulonglong2 xv = xr[q];
                FMA2(acc[2*q],   wp, xv.x);
                FMA2(acc[2*q+1], wp, xv.y);
            }
        }
        // load first half of NEXT chunk (overread lands in weight pad; never consumed)
#pragma unroll
        for (int i=0;i<4;i++) wa[i] = __ldg(wcol + (size_t)(k0+8+i)*1024);
        // compute second half
#pragma unroll
        for (int i=0;i<4;i++){
            unsigned long long wp;
            asm("mov.b64 %0, {%1, %1};" : "=l"(wp) : "r"(__float_as_uint(wb[i])));
            const ulonglong2* xr = (const ulonglong2*)(sx + (size_t)(k0+4+i)*32);
#pragma unroll
            for (int q = 0; q < 8; q++){
                ulonglong2 xv = xr[q];
                FMA2(acc[2*q],   wp, xv.x);
                FMA2(acc[2*q+1], wp, xv.y);
            }
        }
    }
}

// ---------------- fused prologue: weight transposes + state zero + conv fold ----
__global__ void prep_k(const float* __restrict__ aWih, const float* __restrict__ aWhh,
                       const float* __restrict__ dWih, const float* __restrict__ dWhh,
                       const float* __restrict__ locW, const float* __restrict__ convW,
                       const float* __restrict__ convb)
{
    __shared__ float s[32][33];
    int kt = blockIdx.x*32, ut = blockIdx.y*32, z = blockIdx.z;
    int tx = threadIdx.x, ty = threadIdx.y;
    int ft = ty*32 + tx;
    if (z < 3) {
        if (kt >= 1856) return;
        int g = z;
        for (int i = ty; i < 32; i += 8){
            int u = ut + i, k = kt + tx;
            float v = (k < 832) ? aWih[(size_t)(g*1024+u)*832 + k]
                                : aWhh[(size_t)(g*1024+u)*1024 + (k-832)];
            s[i][tx] = v;
        }
        __syncthreads();
        for (int i = ty; i < 32; i += 8){
            int k = kt + i, u = ut + tx;
            g_WAT[((size_t)g*1856 + k)*1024 + u] = s[tx][i];
        }
    } else if (z < 7) {
        int g = z - 3;
        for (int i = ty; i < 32; i += 8){
            int u = ut + i, k = kt + tx;
            float v;
            if      (k < 1024) v = dWih[(size_t)(g*1024+u)*1600 + k];
            else if (k < 2048) v = dWhh[(size_t)(g*1024+u)*1024 + (k-1024)];
            else               v = dWih[(size_t)(g*1024+u)*1600 + 1024 + (k-2048)];
            s[i][tx] = v;
        }
        __syncthreads();
        for (int i = ty; i < 32; i += 8){
            int k = kt + i, u = ut + tx;
            g_WDT[((size_t)g*2624 + k)*1024 + u] = s[tx][i];
        }
    } else {
        int flat = blockIdx.y*82 + blockIdx.x;
        if (flat < 128) {
            int i = flat*256 + ft;
            int n = 128*256;
            for (int j=i; j<NAR*NB; j+=n){ g_AC[0][j]=0.f; g_DC[j]=0.f; g_DH[j]=0.f; }
            for (int j=i; j<NE*NB;  j+=n) g_CTX[j]=0.f;
            for (int j=i; j<NB*NTIN;j+=n){ g_AW[j]=0.f; g_AWC[j]=0.f; }
        }
        if (flat == 0) {
            for (int k=ft; k<64*128; k+=256) {
                int ck = k >> 7, d = k & 127;
                int c = ck >> 5, kk = ck & 31;
                float v = 0.f;
                if (kk < 31)
                    for (int f=0; f<32; f++) v += locW[d*32+f]*convW[f*62 + c*31 + kk];
                g_CW2T[k] = v;
            }
            for (int k=ft; k<128; k+=256) {
                float v = 0.f;
                for (int f=0; f<32; f++) v += locW[k*32+f]*convb[f];
                g_locb2[k] = v;
            }
        }
    }
}

// ---------------- batched GEMM body (pre/post) ----------------
template<int MODE>
__device__ __forceinline__ void gemm_body(int t, int bb, int sb, int row0,
    float* Ws, float* Xs, float* Ss,
    const float* __restrict__ wA, const float* __restrict__ wB,
    const float* __restrict__ xA, const float* __restrict__ bA,
    const float* __restrict__ bB, float* __restrict__ outp)
{
    constexpr int KTOT = (MODE==0)?80:(MODE==1)?256:(MODE==2)?576:1600;
    int tid = threadIdx.x;

    float acc[4][8];
#pragma unroll
    for (int i=0;i<4;i++)
#pragma unroll
        for (int j=0;j<8;j++) acc[i][j] = 0.f;

    int tr = tid >> 2, tc = tid & 3;

    for (int k0 = 0; k0 < KTOT; k0 += 32) {
        for (int i = tid; i < 4096; i += 128) {
            int r = i >> 5, kk = i & 31, kg = k0 + kk;
            float v = 0.f;
            if (kg < KTOT) {
                int row = row0 + r;
                if      constexpr (MODE==0) v = wA[row*80  + kg];
                else if constexpr (MODE==1) v = wA[row*256 + kg];
                else if constexpr (MODE==2) v = wA[row*576 + kg];
                else v = (row<80) ? wA[(size_t)row*1600 + kg] : (row==80) ? wB[kg] : 0.f;
            }
            Ws[kk*129 + r] = v;
        }
        for (int i = tid; i < 1024; i += 128) {
            int c = i >> 5, kk = i & 31, kg = k0 + kk;
            float v = 0.f;
            if (kg < KTOT) {
                if      constexpr (MODE==0) v = (t==0) ? 0.f : xA[((size_t)c*NT + (t-1))*NMELD + kg];
                else if constexpr (MODE==1) v = g_X1[((size_t)t*NB + c)*NPRE + kg];
                else if constexpr (MODE==2) v = xA[((size_t)bb*NTIN + sb*32 + c)*NE + kg];
                else v = (kg<1024)? g_DH[((size_t)(t+1)*NDR + kg)*NB + c]
                                  : g_CTX[((size_t)(t+1)*NE + (kg-1024))*NB + c];
            }
            Xs[kk*33 + c] = v;
        }
        __syncthreads();
#pragma unroll
        for (int kk = 0; kk < 32; kk++) {
            float xr[8], wr[4];
#pragma unroll
            for (int j=0;j<8;j++) xr[j] = Xs[kk*33 + tc*8 + j];
#pragma unroll
            for (int i=0;i<4;i++) wr[i] = Ws[kk*129 + tr*4 + i];
#pragma unroll
            for (int i=0;i<4;i++)
#pragma unroll
                for (int j=0;j<8;j++) acc[i][j] += wr[i]*xr[j];
        }
        __syncthreads();
    }

#pragma unroll
    for (int i=0;i<4;i++)
#pragma unroll
        for (int j=0;j<8;j++) Ss[(tr*4+i)*33 + tc*8 + j] = acc[i][j];
    __syncthreads();

    if constexpr (MODE==0) {
        for (int i = tid; i < 4096; i += 128) {
            int c = i >> 7, r = i & 127;
            float v = Ss[r*33 + c];
            g_X1[((size_t)t*NB + c)*NPRE + row0 + r] = (v > 0.f) ? v : 0.f;
        }
    } else if constexpr (MODE==1) {
        for (int i = tid; i < 4096; i += 128) {
            int r = i >> 5, c = i & 31;
            float v = Ss[r*33 + c];
            g_X2T[((size_t)t*NPRE + row0 + r)*NB + c] = (v > 0.f) ? v : 0.f;
        }
    } else if constexpr (MODE==2) {
        for (int i = tid; i < 4096; i += 128) {
            int d = i & 127, c = i >> 7;
            g_PMEM[((size_t)bb*NTIN + sb*32 + c)*NAD + d] = Ss[d*33 + c];
        }
    } else {
        for (int i = tid; i < 4096; i += 128) {
            int r = i >> 5, c = i & 31;
            if (r < 80)       outp[((size_t)c*NMELD + r)*NT + t] = Ss[r*33 + c] + bA[r];
            else if (r == 80) outp[GATE_OFF + (size_t)c*NT + t]  = Ss[r*33 + c] + bB[0];
        }
    }
}

__global__ void __launch_bounds__(128) gemm0_k(const float* __restrict__ pW1,
                                               const float* __restrict__ dec_in)
{
    __shared__ float Ws[32*129];
    __shared__ float Xs[32*33];
    __shared__ float Ss[128*33];
    gemm_body<0>(blockIdx.y, 0, 0, blockIdx.x*128, Ws, Xs, Ss,
                 pW1, nullptr, dec_in, nullptr, nullptr, nullptr);
}

__global__ void __launch_bounds__(128) gemm12_k(const float* __restrict__ pW2,
                                                const float* __restrict__ memW,
                                                const float* __restrict__ memory)
{
    __shared__ float Ws[32*129];
    __shared__ float Xs[32*33];
    __shared__ float Ss[128*33];
    if (blockIdx.z == 0) {
        if (blockIdx.y < NT)
            gemm_body<1>(blockIdx.y, 0, 0, blockIdx.x*128, Ws, Xs, Ss,
                         pW2, nullptr, nullptr, nullptr, nullptr, nullptr);
    } else {
        if (blockIdx.x == 0)
            gemm_body<2>(0, blockIdx.y >> 4, blockIdx.y & 15, 0, Ws, Xs, Ss,
                         memW, nullptr, memory, nullptr, nullptr, nullptr);
    }
}

__global__ void __launch_bounds__(128) gemm5_k(const float* __restrict__ projW,
                                               const float* __restrict__ gateW,
                                               const float* __restrict__ projb,
                                               const float* __restrict__ gateb,
                                               float* __restrict__ outp)
{
    __shared__ float Ws[32*129];
    __shared__ float Xs[32*33];
    __shared__ float Ss[128*33];
    gemm_body<5>(blockIdx.y, 0, 0, blockIdx.x*128, Ws, Xs, Ss,
                 projW, gateW, nullptr, projb, gateb, outp);
}

// ---------------- combines ----------------
__device__ __forceinline__ void dec_combine(int idx, int tOut,
    const float* __restrict__ dbih, const float* __restrict__ dbhh)
{
    int u = idx >> 5, b = idx & 31;
    float s0=0.f, s1=0.f, s2=0.f, s3=0.f;
#pragma unroll
    for (int sl = 0; sl < 19; sl++){
        const float* p = g_GPD + ((size_t)sl*4*1024 + u)*32 + b;
        s0 += p[0];
        s1 += p[(size_t)1024*32];
        s2 += p[(size_t)2*1024*32];
        s3 += p[(size_t)3*1024*32];
    }
    float gi = s0 + dbih[u]        + dbhh[u];
    float gf = s1 + dbih[1024 + u] + dbhh[1024 + u];
    float gg = s2 + dbih[2048 + u] + dbhh[2048 + u];
    float go = s3 + dbih[3072 + u] + dbhh[3072 + u];
    float cc = g_DC[u*32 + b];
    cc = sigf(gf)*cc + sigf(gi)*tanhf(gg);
    g_DC[u*32 + b] = cc;
    g_DH[((size_t)tOut*NDR + u)*32 + b] = sigf(go)*tanhf(cc);
}

__device__ __forceinline__ void att_combine(int idx, int par,
    const float* __restrict__ abih, const float* __restrict__ abhh)
{
    int u = idx >> 5, b = idx & 31;
    float si=0.f, sf=0.f, sg=0.f;
#pragma unroll
    for (int sl = 0; sl < 18; sl++){
        const float* p = g_GPA + ((size_t)sl*3*1024 + u)*32 + b;
        si += p[0];
        sf += p[(size_t)1024*32];
        sg += p[(size_t)2*1024*32];
    }
    si += abih[u]        + abhh[u];
    sf += abih[1024 + u] + abhh[1024 + u];
    sg += abih[2048 + u] + abhh[2048 + u];
    float cp = g_AC[par][u*32 + b];
    float nv = sigf(sf)*cp + sigf(si)*tanhf(sg);    // ah = ac quirk
    g_AC[par^1][u*32 + b] = nv;
    g_ACT[b*NAR + u] = nv;                          // transposed copy for P3
}

// ---------------- the persistent decoder ----------------
__global__ void __launch_bounds__(NTHR, 1) decoder_persist(
    const float* __restrict__ abih, const float* __restrict__ abhh,
    const float* __restrict__ dbih, const float* __restrict__ dbhh,
    const float* __restrict__ qW,   const float* __restrict__ vW,
    const float* __restrict__ memory, const int* __restrict__ mlen,
    float* __restrict__ outp)
{
    __shared__ __align__(16) float sX[9728];   // GEMV staging / conv weights / ctx partials
    __shared__ __align__(16) float sMisc[2304];
    __shared__ int sLen[32];

    float* sAH  = sMisc;             // 1024
    float* sQ   = sMisc + 1024;      // 128
    float* sV   = sMisc + 1152;      // 128
    float* sRed = sMisc + 1280;      // 64 used
    float* sAWS = sMisc + 1792;      // 512

    const int tid  = threadIdx.x;
    const int bid  = blockIdx.x;
    const int lane = tid & 31, wid = tid >> 5;

    unsigned gen = g_bar_flag;

    if (tid < 32) sLen[tid] = mlen[tid];

    // ---- task precompute ----
    const int aseg = bid / 6;
    const int agu  = (bid % 6)*16 + wid;             // 0..95
    const int akb  = aseg*1856/18;
    const int ake  = (aseg+1)*1856/18;
    const int aklen8 = ((ake - akb) + 7) & ~7;
    const int ag   = agu >> 5;
    const int au   = (agu & 31)*32 + lane;
    const int cseg = (bid - 108) >> 3;
    const int cgu  = ((bid - 108) & 7)*16 + wid;     // 0..127
    const int ckb  = (bid >= 108) ? cseg*576/5 : 0;
    const int cke  = (bid >= 108) ? (cseg+1)*576/5 : 0;
    const int cklen8 = ((cke - ckb) + 7) & ~7;
    const int cg   = cgu >> 5;
    const int cu   = (cgu & 31)*32 + lane;
    const int dseg = (bid - 32) >> 3;
    const int dgu  = ((bid - 32) & 7)*16 + wid;      // 0..127
    const int dkb  = (bid >= 32 && bid < 144) ? dseg*2048/14 : 0;
    const int dke  = (bid >= 32 && bid < 144) ? (dseg+1)*2048/14 : 0;
    const int dklen8 = ((dke - dkb) + 7) & ~7;
    const int dg   = dgu >> 5;
    const int du   = (dgu & 31)*32 + lane;

    const int lt0 = bid*4096/148, lt1 = (bid+1)*4096/148;

    __syncthreads();

    for (int t = 0; t < NT; t++) {
        const int par = t & 1;

        // ============ P1: att GEMV + ctx-part dec GEMV (prev step) =========
        if (bid < 108) {
            int a0 = akb, a1 = min(ake, 256);
            if (a1 > a0) copy4(sX + (a0-akb)*32, g_X2T + ((size_t)t*NPRE + a0)*32, (a1-a0)*32, tid);
            int b0 = max(akb, 256), b1 = min(ake, 832);
            if (b1 > b0) copy4(sX + (b0-akb)*32, g_CTX + ((size_t)t*NE + (b0-256))*32, (b1-b0)*32, tid);
            int c0 = max(akb, 832);
            if (ake > c0) copy4(sX + (c0-akb)*32, g_AC[par] + (c0-832)*32, (ake-c0)*32, tid);
            zpad(sX, ake - akb, aklen8, tid);
            __syncthreads();
            unsigned long long acc[16];
#pragma unroll
            for (int q=0;q<16;q++) acc[q] = 0ull;
            gemv2(g_WAT + ((size_t)ag*1856 + akb)*1024 + au, sX, aklen8, acc);
            ulonglong2* dst = (ulonglong2*)(g_GPA + ((size_t)(aseg*3 + ag)*1024 + au)*32);
#pragma unroll
            for (int q=0;q<8;q++) dst[q] = make_ulonglong2(acc[2*q], acc[2*q+1]);
        } else if (t > 0) {
            copy4(sX, g_CTX + ((size_t)t*NE + ckb)*32, (cke-ckb)*32, tid);
            zpad(sX, cke - ckb, cklen8, tid);
            __syncthreads();
            unsigned long long acc[16];
#pragma unroll
            for (int q=0;q<16;q++) acc[q] = 0ull;
            gemv2(g_WDT + ((size_t)cg*2624 + 2048 + ckb)*1024 + cu, sX, cklen8, acc);
            ulonglong2* dst = (ulonglong2*)(g_GPD + ((size_t)((14+cseg)*4 + cg)*1024 + cu)*32);
#pragma unroll
            for (int q=0;q<8;q++) dst[q] = make_ulonglong2(acc[2*q], acc[2*q+1]);
        }
        gsync(gen);

        // ============ P2: combines + location conv (len-skipped, scalar) ===
        if (bid < 64) att_combine(bid*NTHR + tid, par, abih, abhh);
        else if (bid < 128 && t > 0) dec_combine((bid-64)*NTHR + tid, t, dbih, dbhh);

        for (int i=tid; i<8192; i+=NTHR) sX[i] = g_CW2T[i];
        __syncthreads();
        {
            int rep = tid >> 7;
            int d = tid & 127;
            for (int task = lt0 + rep; task < lt1; task += 4) {
                int b = task >> 7, s0 = (task & 127)*4;
                if (s0 >= sLen[b]) continue;          // dead positions: aw==0 beyond len
                float wa[34], wb[34];
#pragma unroll
                for (int j=0; j<34; j++){
                    int sg2 = s0 - 15 + j;
                    bool ok = (sg2 >= 0 && sg2 < NTIN);
                    wa[j] = ok ? g_AW [b*NTIN + sg2] : 0.f;
                    wb[j] = ok ? g_AWC[b*NTIN + sg2] : 0.f;
                }
                float a0=0.f, a1=0.f, a2=0.f, a3=0.f;
#pragma unroll
                for (int k=0; k<31; k++){
                    float w = sX[k*128 + d];
                    a0 += w*wa[k]; a1 += w*wa[k+1]; a2 += w*wa[k+2]; a3 += w*wa[k+3];
                }
#pragma unroll
                for (int k=0; k<31; k++){
                    float w = sX[(32+k)*128 + d];
                    a0 += w*wb[k]; a1 += w*wb[k+1]; a2 += w*wb[k+2]; a3 += w*wb[k+3];
                }
                float* dstL = &g_LOC[((size_t)b*NTIN + s0)*NAD + d];
                dstL[0] = a0; dstL[128] = a1; dstL[256] = a2; dstL[384] = a3;
            }
        }
        gsync(gen);

        // ============ P3: attention (blocks 0..31) | dec GEMV K=2048 =======
        if (bid < 32) {
            const int b = bid;
            const int len = sLen[b];
            for (int i=tid; i<1024; i+=NTHR) sAH[i] = g_ACT[b*NAR + i];   // coalesced
            if (tid < 128) sV[tid] = vW[tid];
            __syncthreads();
            for (int dd = 0; dd < 8; dd++) {
                int d = wid*8 + dd;
                const float* qr = qW + (size_t)d*1024;
                float s = 0.f;
                for (int uu = lane; uu < 1024; uu += 32) s += qr[uu]*sAH[uu];
#pragma unroll
                for (int o=16; o>0; o>>=1) s += __shfl_down_sync(0xffffffffu, s, o);
                if (lane == 0) sQ[d] = s + g_locb2[d];
            }
            __syncthreads();
            // energy for s = tid (only for live positions)
            float en = 0.f;
            if (tid < len) {
                const float4* p4 = (const float4*)(g_PMEM + ((size_t)b*NTIN + tid)*NAD);
                const float4* l4 = (const float4*)(g_LOC  + ((size_t)b*NTIN + tid)*NAD);
                float acc = 0.f;
#pragma unroll 8
                for (int dq = 0; dq < 32; dq++) {
                    float4 p = p4[dq], l = l4[dq];
                    int d = dq*4;
                    acc += sV[d+0]*ftanh(sQ[d+0] + p.x + l.x);
                    acc += sV[d+1]*ftanh(sQ[d+1] + p.y + l.y);
                    acc += sV[d+2]*ftanh(sQ[d+2] + p.z + l.z);
                    acc += sV[d+3]*ftanh(sQ[d+3] + p.w + l.w);
                }
                en = acc;
            }
            // shuffle-based max reduction
            float mval = (tid < len) ? en : -1e30f;
#pragma unroll
            for (int o=16; o>0; o>>=1) mval = fmaxf(mval, __shfl_xor_sync(0xffffffffu, mval, o));
            if (lane == 0) sRed[wid] = mval;
            __syncthreads();
            if (tid < 16) {
                float v = sRed[tid];
#pragma unroll
                for (int o=8; o>0; o>>=1) v = fmaxf(v, __shfl_xor_sync(0xffffu, v, o));
                if (tid == 0) sRed[32] = v;
            }
            __syncthreads();
            float mx = sRed[32];
            float e0 = (tid < len) ? expf(en - mx) : 0.f;
            float sval = e0;
#pragma unroll
            for (int o=16; o>0; o>>=1) sval += __shfl_xor_sync(0xffffffffu, sval, o);
            if (lane == 0) sRed[wid] = sval;
            __syncthreads();
            if (tid < 16) {
                float v = sRed[tid];
#pragma unroll
                for (int o=8; o>0; o>>=1) v += __shfl_xor_sync(0xffffu, v, o);
                if (tid == 0) sRed[33] = v;
            }
            __syncthreads();
            float inv = 1.f/sRed[33];
            float a0 = e0*inv;
            sAWS[tid] = a0;
            g_AW [b*NTIN + tid]  = a0;
            g_AWC[b*NTIN + tid] += a0;
            outp[ALIGN_OFF + ((size_t)b*NT + t)*NTIN + tid] = a0;
            __syncthreads();
            // context: warp-split over s (len-bounded), partials in sX[16][576]
            {
                float4 a40=make_float4(0,0,0,0), a41=a40, a42=a40, a43=a40, a44=a40;
                int sbase = wid*32;
                int send = min(sbase + 32, len);
                for (int s = sbase; s < send; s++){
                    float a = sAWS[s];
                    const float4* m4 = (const float4*)(memory + ((size_t)b*NTIN + s)*NE);
                    float4 v;
                    v = m4[lane];      a40.x+=a*v.x; a40.y+=a*v.y; a40.z+=a*v.z; a40.w+=a*v.w;
                    v = m4[lane+32];   a41.x+=a*v.x; a41.y+=a*v.y; a41.z+=a*v.z; a41.w+=a*v.w;
                    v = m4[lane+64];   a42.x+=a*v.x; a42.y+=a*v.y; a42.z+=a*v.z; a42.w+=a*v.w;
                    v = m4[lane+96];   a43.x+=a*v.x; a43.y+=a*v.y; a43.z+=a*v.z; a43.w+=a*v.w;
                    if (lane < 16){ v = m4[lane+128]; a44.x+=a*v.x; a44.y+=a*v.y; a44.z+=a*v.z; a44.w+=a*v.w; }
                }
                float4* p4 = (float4*)(sX + wid*576);
                p4[lane]     = a40;
                p4[lane+32]  = a41;
                p4[lane+64]  = a42;
                p4[lane+96]  = a43;
                if (lane < 16) p4[lane+128] = a44;
            }
            __syncthreads();
            {
                float s1 = 0.f;
#pragma unroll
                for (int w2=0; w2<16; w2++) s1 += sX[w2*576 + tid];
                g_CTX[((size_t)(t+1)*NE + tid)*32 + b] = s1;
                if (tid < 64){
                    float s2 = 0.f;
#pragma unroll
                    for (int w2=0; w2<16; w2++) s2 += sX[w2*576 + 512 + tid];
                    g_CTX[((size_t)(t+1)*NE + 512 + tid)*32 + b] = s2;
                }
            }
        } else if (bid < 144) {
            int a0 = dkb, a1 = min(dke, 1024);
            if (a1 > a0) copy4(sX + (a0-dkb)*32, g_AC[par^1] + a0*32, (a1-a0)*32, tid);
            int b0 = max(dkb, 1024);
            if (dke > b0) copy4(sX + (b0-dkb)*32, g_DH + ((size_t)t*NDR + (b0-1024))*32, (dke-b0)*32, tid);
            zpad(sX, dke - dkb, dklen8, tid);
            __syncthreads();
            unsigned long long acc[16];
#pragma unroll
            for (int q=0;q<16;q++) acc[q] = 0ull;
            gemv2(g_WDT + ((size_t)dg*2624 + dkb)*1024 + du, sX, dklen8, acc);
            ulonglong2* dst = (ulonglong2*)(g_GPD + ((size_t)(dseg*4 + dg)*1024 + du)*32);
#pragma unroll
            for (int q=0;q<8;q++) dst[q] = make_ulonglong2(acc[2*q], acc[2*q+1]);
        }
        gsync(gen);
    }

    // ---- epilogue: ctx GEMV for step NT-1, then final dec combine ----
    if (bid >= 108) {
        copy4(sX, g_CTX + ((size_t)NT*NE + ckb)*32, (cke-ckb)*32, tid);
        zpad(sX, cke - ckb, cklen8, tid);
        __syncthreads();
        unsigned long long acc[16];
#pragma unroll
        for (int q=0;q<16;q++) acc[q] = 0ull;
        gemv2(g_WDT + ((size_t)cg*2624 + 2048 + ckb)*1024 + cu, sX, cklen8, acc);
        ulonglong2* dst = (ulonglong2*)(g_GPD + ((size_t)((14+cseg)*4 + cg)*1024 + cu)*32);
#pragma unroll
        for (int q=0;q<8;q++) dst[q] = make_ulonglong2(acc[2*q], acc[2*q+1]);
    }
    gsync(gen);
    if (bid >= 64 && bid < 128) dec_combine((bid-64)*NTHR + tid, NT, dbih, dbhh);
}

// ---------------- launch ----------------
extern "C" void kernel_launch(void* const* d_in, const int* in_sizes, int n_in,
                              void* d_out, int out_size)
{
    const float* memory  = (const float*)d_in[0];
    const float* dec_in  = (const float*)d_in[1];
    const float* pW1     = (const float*)d_in[2];
    const float* pW2     = (const float*)d_in[3];
    const float* aWih    = (const float*)d_in[4];
    const float* aWhh    = (const float*)d_in[5];
    const float* abih    = (const float*)d_in[6];
    const float* abhh    = (const float*)d_in[7];
    const float* qW      = (const float*)d_in[8];
    const float* memW    = (const float*)d_in[9];
    const float* convW   = (const float*)d_in[10];
    const float* convb   = (const float*)d_in[11];
    const float* locW    = (const float*)d_in[12];
    const float* vW      = (const float*)d_in[13];
    const float* dWih    = (const float*)d_in[14];
    const float* dWhh    = (const float*)d_in[15];
    const float* dbih    = (const float*)d_in[16];
    const float* dbhh    = (const float*)d_in[17];
    const float* projW   = (const float*)d_in[18];
    const float* projb   = (const float*)d_in[19];
    const float* gateW   = (const float*)d_in[20];
    const float* gateb   = (const float*)d_in[21];
    const int*   mlen    = (const int*)  d_in[22];
    float* outp = (float*)d_out;

    prep_k<<<dim3(82,32,8), dim3(32,8)>>>(aWih, aWhh, dWih, dWhh, locW, convW, convb); // 0
    gemm0_k<<<dim3(2,NT),128>>>(pW1, dec_in);                                          // 1
    gemm12_k<<<dim3(2,512,2),128>>>(pW2, memW, memory);                                // 2
    decoder_persist<<<148,NTHR>>>(abih, abhh, dbih, dbhh, qW, vW, memory, mlen, outp); // 3
    gemm5_k<<<dim3(1,NT),128>>>(projW, gateW, projb, gateb, outp);                     // 4
}

// round 17
// speedup vs baseline: 1.1366x; 1.1366x over previous
#include <cuda_runtime.h>
#include <cuda_fp16.h>
#include <math.h>
#include <stdint.h>

#define NB    32
#define NTIN  512
#define NE    576
#define NT    400
#define NMELD 80
#define NPRE  256
#define NAR   1024
#define NDR   1024
#define NAD   128

#define GATE_OFF  (NB*NMELD*NT)
#define ALIGN_OFF (GATE_OFF + NB*NT)

#define NTHR 512

// ---------------- static device scratch ----------------
// fp16 weights, packed half2 over k-pairs: [g][kpair][u]
__device__ __half2 g_WATh[(size_t)3*928*1024 + 8192];    // att (k=1856 -> 928 pairs) +pad
__device__ __half2 g_WDTh[(size_t)4*1312*1024 + 8192];   // dec (k=2624 -> 1312 pairs, [ah|dh|ctx]) +pad
__device__ float g_X1 [(size_t)NT*NB*NPRE];           // [t][b][k]
__device__ float g_X2T[(size_t)NT*NPRE*NB];           // [t][k][b]
__device__ float g_PMEM[(size_t)NB*NTIN*NAD];         // [b][s][d]
__device__ float g_LOC [(size_t)NB*NTIN*NAD];         // [b][s][d]
__device__ float g_CW2T[64*128];                      // [ck][d]
__device__ float g_locb2[128];
__device__ float g_AC[2][NAR*NB];                     // [u][b], ah == ac
__device__ float g_ACT[NB*NAR];                       // [b][u] transposed ah copy
__device__ float g_DC[NDR*NB];                        // [u][b]
__device__ float g_DH[(size_t)(NT+1)*NDR*NB];         // [t][u][b]
__device__ float g_CTX[(size_t)(NT+1)*NE*NB];         // [t][e][b]
__device__ float g_AW [NB*NTIN];
__device__ float g_AWC[NB*NTIN];
__device__ float g_GPA[(size_t)18*3*1024*32];         // att partials [seg][g][u][b]
__device__ float g_GPD[(size_t)19*4*1024*32];         // dec partials [slot][g][u][b]

__device__ unsigned g_bar_arrive;
__device__ volatile unsigned g_bar_flag;

__device__ __forceinline__ float sigf(float x){ return 1.f/(1.f+expf(-x)); }
__device__ __forceinline__ float ftanh(float x){
    x = fminf(8.f, fmaxf(-8.f, x));
    float e = __expf(2.f*x);
    return (e-1.f)/(e+1.f);
}

__device__ __forceinline__ void gsync(unsigned &gen)
{
    __syncthreads();
    gen++;
    if (threadIdx.x == 0){
        __threadfence();
        unsigned a = atomicAdd(&g_bar_arrive, 1u);
        if (a == gridDim.x - 1){
            g_bar_arrive = 0;
            __threadfence();
            g_bar_flag = gen;
        } else {
            while (g_bar_flag < gen) { __nanosleep(40); }
        }
        __threadfence();
    }
    __syncthreads();
}

__device__ __forceinline__ void copy4(float* dst, const float* src, int nfl, int tid)
{
    const float4* s4 = (const float4*)src;
    float4* d4 = (float4*)dst;
    int n4 = nfl >> 2;
    for (int i = tid; i < n4; i += NTHR) d4[i] = s4[i];
}

__device__ __forceinline__ void zpad(float* sx, int klen, int klenp, int tid)
{
    for (int i = klen*32 + tid; i < klenp*32; i += NTHR) sx[i] = 0.f;
}

#define FMA2(acc, a, b) asm("fma.rn.f32x2 %0, %1, %2, %0;" : "+l"(acc) : "l"(a), "l"(b))

// coalesced half2-weight GEMV: lane owns unit u, 32 b in 16 packed f32x2 accs.
// Each half2 load covers 2 consecutive k's. 4-load (8 k) batched prefetch.
// klen8 multiple of 8; sx zero-padded; wcol padded for benign overread.
__device__ __forceinline__ void gemv2h(const __half2* __restrict__ wcol,
                                       const float* __restrict__ sx, int klen8,
                                       unsigned long long* acc)
{
    const int np = klen8 >> 1;          // pairs, multiple of 4
    for (int p0 = 0; p0 < np; p0 += 4){
        __half2 w[4];
#pragma unroll
        for (int i=0;i<4;i++) w[i] = __ldg(wcol + (size_t)(p0+i)*1024);
#pragma unroll
        for (int i=0;i<4;i++){
            float2 wf = __half22float2(w[i]);
            unsigned long long wp0, wp1;
            asm("mov.b64 %0, {%1, %1};" : "=l"(wp0) : "r"(__float_as_uint(wf.x)));
            asm("mov.b64 %0, {%1, %1};" : "=l"(wp1) : "r"(__float_as_uint(wf.y)));
            const ulonglong2* xr0 = (const ulonglong2*)(sx + (size_t)(2*(p0+i))*32);
            const ulonglong2* xr1 = (const ulonglong2*)(sx + (size_t)(2*(p0+i)+1)*32);
#pragma unroll
            for (int q = 0; q < 8; q++){
                ulonglong2 xv = xr0[q];
                FMA2(acc[2*q],   wp0, xv.x);
                FMA2(acc[2*q+1], wp0, xv.y);
            }
#pragma unroll
            for (int q = 0; q < 8; q++){
                ulonglong2 xv = xr1[q];
                FMA2(acc[2*q],   wp1, xv.x);
                FMA2(acc[2*q+1], wp1, xv.y);
            }
        }
    }
}

// ---------------- fused prologue: weight transposes (fp16) + state zero + conv fold
__global__ void prep_k(const float* __restrict__ aWih, const float* __restrict__ aWhh,
                       const float* __restrict__ dWih, const float* __restrict__ dWhh,
                       const float* __restrict__ locW, const float* __restrict__ convW,
                       const float* __restrict__ convb)
{
    __shared__ float s[32][33];
    int kt = blockIdx.x*32, ut = blockIdx.y*32, z = blockIdx.z;
    int tx = threadIdx.x, ty = threadIdx.y;
    int ft = ty*32 + tx;
    if (z < 3) {
        if (kt >= 1856) return;
        int g = z;
        for (int i = ty; i < 32; i += 8){
            int u = ut + i, k = kt + tx;
            float v = (k < 832) ? aWih[(size_t)(g*1024+u)*832 + k]
                                : aWhh[(size_t)(g*1024+u)*1024 + (k-832)];
            s[i][tx] = v;
        }
        __syncthreads();
        for (int i = ty; i < 16; i += 8){
            int kp = (kt >> 1) + i, u = ut + tx;
            g_WATh[((size_t)g*928 + kp)*1024 + u] =
                __floats2half2_rn(s[tx][2*i], s[tx][2*i+1]);
        }
    } else if (z < 7) {
        int g = z - 3;
        for (int i = ty; i < 32; i += 8){
            int u = ut + i, k = kt + tx;
            float v;
            if      (k < 1024) v = dWih[(size_t)(g*1024+u)*1600 + k];
            else if (k < 2048) v = dWhh[(size_t)(g*1024+u)*1024 + (k-1024)];
            else               v = dWih[(size_t)(g*1024+u)*1600 + 1024 + (k-2048)];
            s[i][tx] = v;
        }
        __syncthreads();
        for (int i = ty; i < 16; i += 8){
            int kp = (kt >> 1) + i, u = ut + tx;
            g_WDTh[((size_t)g*1312 + kp)*1024 + u] =
                __floats2half2_rn(s[tx][2*i], s[tx][2*i+1]);
        }
    } else {
        int flat = blockIdx.y*82 + blockIdx.x;
        if (flat < 128) {
            int i = flat*256 + ft;
            int n = 128*256;
            for (int j=i; j<NAR*NB; j+=n){ g_AC[0][j]=0.f; g_DC[j]=0.f; g_DH[j]=0.f; }
            for (int j=i; j<NE*NB;  j+=n) g_CTX[j]=0.f;
            for (int j=i; j<NB*NTIN;j+=n){ g_AW[j]=0.f; g_AWC[j]=0.f; }
        }
        if (flat == 0) {
            for (int k=ft; k<64*128; k+=256) {
                int ck = k >> 7, d = k & 127;
                int c = ck >> 5, kk = ck & 31;
                float v = 0.f;
                if (kk < 31)
                    for (int f=0; f<32; f++) v += locW[d*32+f]*convW[f*62 + c*31 + kk];
                g_CW2T[k] = v;
            }
            for (int k=ft; k<128; k+=256) {
                float v = 0.f;
                for (int f=0; f<32; f++) v += locW[k*32+f]*convb[f];
                g_locb2[k] = v;
            }
        }
    }
}

// ---------------- batched GEMM body (pre/post, fp32) ----------------
template<int MODE>
__device__ __forceinline__ void gemm_body(int t, int bb, int sb, int row0,
    float* Ws, float* Xs, float* Ss,
    const float* __restrict__ wA, const float* __restrict__ wB,
    const float* __restrict__ xA, const float* __restrict__ bA,
    const float* __restrict__ bB, float* __restrict__ outp)
{
    constexpr int KTOT = (MODE==0)?80:(MODE==1)?256:(MODE==2)?576:1600;
    int tid = threadIdx.x;

    float acc[4][8];
#pragma unroll
    for (int i=0;i<4;i++)
#pragma unroll
        for (int j=0;j<8;j++) acc[i][j] = 0.f;

    int tr = tid >> 2, tc = tid & 3;

    for (int k0 = 0; k0 < KTOT; k0 += 32) {
        for (int i = tid; i < 4096; i += 128) {
            int r = i >> 5, kk = i & 31, kg = k0 + kk;
            float v = 0.f;
            if (kg < KTOT) {
                int row = row0 + r;
                if      constexpr (MODE==0) v = wA[row*80  + kg];
                else if constexpr (MODE==1) v = wA[row*256 + kg];
                else if constexpr (MODE==2) v = wA[row*576 + kg];
                else v = (row<80) ? wA[(size_t)row*1600 + kg] : (row==80) ? wB[kg] : 0.f;
            }
            Ws[kk*129 + r] = v;
        }
        for (int i = tid; i < 1024; i += 128) {
            int c = i >> 5, kk = i & 31, kg = k0 + kk;
            float v = 0.f;
            if (kg < KTOT) {
                if      constexpr (MODE==0) v = (t==0) ? 0.f : xA[((size_t)c*NT + (t-1))*NMELD + kg];
                else if constexpr (MODE==1) v = g_X1[((size_t)t*NB + c)*NPRE + kg];
                else if constexpr (MODE==2) v = xA[((size_t)bb*NTIN + sb*32 + c)*NE + kg];
                else v = (kg<1024)? g_DH[((size_t)(t+1)*NDR + kg)*NB + c]
                                  : g_CTX[((size_t)(t+1)*NE + (kg-1024))*NB + c];
            }
            Xs[kk*33 + c] = v;
        }
        __syncthreads();
#pragma unroll
        for (int kk = 0; kk < 32; kk++) {
            float xr[8], wr[4];
#pragma unroll
            for (int j=0;j<8;j++) xr[j] = Xs[kk*33 + tc*8 + j];
#pragma unroll
            for (int i=0;i<4;i++) wr[i] = Ws[kk*129 + tr*4 + i];
#pragma unroll
            for (int i=0;i<4;i++)
#pragma unroll
                for (int j=0;j<8;j++) acc[i][j] += wr[i]*xr[j];
        }
        __syncthreads();
    }

#pragma unroll
    for (int i=0;i<4;i++)
#pragma unroll
        for (int j=0;j<8;j++) Ss[(tr*4+i)*33 + tc*8 + j] = acc[i][j];
    __syncthreads();

    if constexpr (MODE==0) {
        for (int i = tid; i < 4096; i += 128) {
            int c = i >> 7, r = i & 127;
            float v = Ss[r*33 + c];
            g_X1[((size_t)t*NB + c)*NPRE + row0 + r] = (v > 0.f) ? v : 0.f;
        }
    } else if constexpr (MODE==1) {
        for (int i = tid; i < 4096; i += 128) {
            int r = i >> 5, c = i & 31;
            float v = Ss[r*33 + c];
            g_X2T[((size_t)t*NPRE + row0 + r)*NB + c] = (v > 0.f) ? v : 0.f;
        }
    } else if constexpr (MODE==2) {
        for (int i = tid; i < 4096; i += 128) {
            int d = i & 127, c = i >> 7;
            g_PMEM[((size_t)bb*NTIN + sb*32 + c)*NAD + d] = Ss[d*33 + c];
        }
    } else {
        for (int i = tid; i < 4096; i += 128) {
            int r = i >> 5, c = i & 31;
            if (r < 80)       outp[((size_t)c*NMELD + r)*NT + t] = Ss[r*33 + c] + bA[r];
            else if (r == 80) outp[GATE_OFF + (size_t)c*NT + t]  = Ss[r*33 + c] + bB[0];
        }
    }
}

__global__ void __launch_bounds__(128) gemm0_k(const float* __restrict__ pW1,
                                               const float* __restrict__ dec_in)
{
    __shared__ float Ws[32*129];
    __shared__ float Xs[32*33];
    __shared__ float Ss[128*33];
    gemm_body<0>(blockIdx.y, 0, 0, blockIdx.x*128, Ws, Xs, Ss,
                 pW1, nullptr, dec_in, nullptr, nullptr, nullptr);
}

__global__ void __launch_bounds__(128) gemm12_k(const float* __restrict__ pW2,
                                                const float* __restrict__ memW,
                                                const float* __restrict__ memory)
{
    __shared__ float Ws[32*129];
    __shared__ float Xs[32*33];
    __shared__ float Ss[128*33];
    if (blockIdx.z == 0) {
        if (blockIdx.y < NT)
            gemm_body<1>(blockIdx.y, 0, 0, blockIdx.x*128, Ws, Xs, Ss,
                         pW2, nullptr, nullptr, nullptr, nullptr, nullptr);
    } else {
        if (blockIdx.x == 0)
            gemm_body<2>(0, blockIdx.y >> 4, blockIdx.y & 15, 0, Ws, Xs, Ss,
                         memW, nullptr, memory, nullptr, nullptr, nullptr);
    }
}

__global__ void __launch_bounds__(128) gemm5_k(const float* __restrict__ projW,
                                               const float* __restrict__ gateW,
                                               const float* __restrict__ projb,
                                               const float* __restrict__ gateb,
                                               float* __restrict__ outp)
{
    __shared__ float Ws[32*129];
    __shared__ float Xs[32*33];
    __shared__ float Ss[128*33];
    gemm_body<5>(blockIdx.y, 0, 0, blockIdx.x*128, Ws, Xs, Ss,
                 projW, gateW, nullptr, projb, gateb, outp);
}

// ---------------- combines ----------------
__device__ __forceinline__ void dec_combine(int idx, int tOut,
    const float* __restrict__ dbih, const float* __restrict__ dbhh)
{
    int u = idx >> 5, b = idx & 31;
    float s0=0.f, s1=0.f, s2=0.f, s3=0.f;
#pragma unroll
    for (int sl = 0; sl < 19; sl++){
        const float* p = g_GPD + ((size_t)sl*4*1024 + u)*32 + b;
        s0 += p[0];
        s1 += p[(size_t)1024*32];
        s2 += p[(size_t)2*1024*32];
        s3 += p[(size_t)3*1024*32];
    }
    float gi = s0 + dbih[u]        + dbhh[u];
    float gf = s1 + dbih[1024 + u] + dbhh[1024 + u];
    float gg = s2 + dbih[2048 + u] + dbhh[2048 + u];
    float go = s3 + dbih[3072 + u] + dbhh[3072 + u];
    float cc = g_DC[u*32 + b];
    cc = sigf(gf)*cc + sigf(gi)*tanhf(gg);
    g_DC[u*32 + b] = cc;
    g_DH[((size_t)tOut*NDR + u)*32 + b] = sigf(go)*tanhf(cc);
}

__device__ __forceinline__ void att_combine(int idx, int par,
    const float* __restrict__ abih, const float* __restrict__ abhh)
{
    int u = idx >> 5, b = idx & 31;
    float si=0.f, sf=0.f, sg=0.f;
#pragma unroll
    for (int sl = 0; sl < 18; sl++){
        const float* p = g_GPA + ((size_t)sl*3*1024 + u)*32 + b;
        si += p[0];
        sf += p[(size_t)1024*32];
        sg += p[(size_t)2*1024*32];
    }
    si += abih[u]        + abhh[u];
    sf += abih[1024 + u] + abhh[1024 + u];
    sg += abih[2048 + u] + abhh[2048 + u];
    float cp = g_AC[par][u*32 + b];
    float nv = sigf(sf)*cp + sigf(si)*tanhf(sg);    // ah = ac quirk
    g_AC[par^1][u*32 + b] = nv;
    g_ACT[b*NAR + u] = nv;                          // transposed copy for P3
}

// ---------------- the persistent decoder ----------------
__global__ void __launch_bounds__(NTHR, 1) decoder_persist(
    const float* __restrict__ abih, const float* __restrict__ abhh,
    const float* __restrict__ dbih, const float* __restrict__ dbhh,
    const float* __restrict__ qW,   const float* __restrict__ vW,
    const float* __restrict__ memory, const int* __restrict__ mlen,
    float* __restrict__ outp)
{
    __shared__ __align__(16) float sX[9728];   // GEMV staging / conv weights / ctx partials
    __shared__ __align__(16) float sMisc[2304];
    __shared__ int sLen[32];

    float* sAH  = sMisc;             // 1024
    float* sQ   = sMisc + 1024;      // 128
    float* sV   = sMisc + 1152;      // 128
    float* sRed = sMisc + 1280;      // 64 used
    float* sAWS = sMisc + 1792;      // 512

    const int tid  = threadIdx.x;
    const int bid  = blockIdx.x;
    const int lane = tid & 31, wid = tid >> 5;

    unsigned gen = g_bar_flag;

    if (tid < 32) sLen[tid] = mlen[tid];

    // ---- task precompute (k-boundaries rounded to even for half2) ----
    const int aseg = bid / 6;
    const int agu  = (bid % 6)*16 + wid;             // 0..95
    const int akb  = (aseg*1856/18) & ~1;
    const int ake  = ((aseg+1)*1856/18) & ~1;
    const int aklen8 = ((ake - akb) + 7) & ~7;
    const int ag   = agu >> 5;
    const int au   = (agu & 31)*32 + lane;
    const int cseg = (bid - 108) >> 3;
    const int cgu  = ((bid - 108) & 7)*16 + wid;     // 0..127
    const int ckb  = (bid >= 108) ? ((cseg*576/5) & ~1) : 0;
    const int cke  = (bid >= 108) ? (((cseg+1)*576/5) & ~1) : 0;
    const int cklen8 = ((cke - ckb) + 7) & ~7;
    const int cg   = cgu >> 5;
    const int cu   = (cgu & 31)*32 + lane;
    const int dseg = (bid - 32) >> 3;
    const int dgu  = ((bid - 32) & 7)*16 + wid;      // 0..127
    const int dkb  = (bid >= 32 && bid < 144) ? ((dseg*2048/14) & ~1) : 0;
    const int dke  = (bid >= 32 && bid < 144) ? (((dseg+1)*2048/14) & ~1) : 0;
    const int dklen8 = ((dke - dkb) + 7) & ~7;
    const int dg   = dgu >> 5;
    const int du   = (dgu & 31)*32 + lane;

    const int lt0 = bid*4096/148, lt1 = (bid+1)*4096/148;

    __syncthreads();

    for (int t = 0; t < NT; t++) {
        const int par = t & 1;

        // ============ P1: att GEMV + ctx-part dec GEMV (prev step) =========
        if (bid < 108) {
            int a0 = akb, a1 = min(ake, 256);
            if (a1 > a0) copy4(sX + (a0-akb)*32, g_X2T + ((size_t)t*NPRE + a0)*32, (a1-a0)*32, tid);
            int b0 = max(akb, 256), b1 = min(ake, 832);
            if (b1 > b0) copy4(sX + (b0-akb)*32, g_CTX + ((size_t)t*NE + (b0-256))*32, (b1-b0)*32, tid);
            int c0 = max(akb, 832);
            if (ake > c0) copy4(sX + (c0-akb)*32, g_AC[par] + (c0-832)*32, (ake-c0)*32, tid);
            zpad(sX, ake - akb, aklen8, tid);
            __syncthreads();
            unsigned long long acc[16];
#pragma unroll
            for (int q=0;q<16;q++) acc[q] = 0ull;
            gemv2h(g_WATh + ((size_t)ag*928 + (akb>>1))*1024 + au, sX, aklen8, acc);
            ulonglong2* dst = (ulonglong2*)(g_GPA + ((size_t)(aseg*3 + ag)*1024 + au)*32);
#pragma unroll
            for (int q=0;q<8;q++) dst[q] = make_ulonglong2(acc[2*q], acc[2*q+1]);
        } else if (t > 0) {
            copy4(sX, g_CTX + ((size_t)t*NE + ckb)*32, (cke-ckb)*32, tid);
            zpad(sX, cke - ckb, cklen8, tid);
            __syncthreads();
            unsigned long long acc[16];
#pragma unroll
            for (int q=0;q<16;q++) acc[q] = 0ull;
            gemv2h(g_WDTh + ((size_t)cg*1312 + 1024 + (ckb>>1))*1024 + cu, sX, cklen8, acc);
            ulonglong2* dst = (ulonglong2*)(g_GPD + ((size_t)((14+cseg)*4 + cg)*1024 + cu)*32);
#pragma unroll
            for (int q=0;q<8;q++) dst[q] = make_ulonglong2(acc[2*q], acc[2*q+1]);
        }
        gsync(gen);

        // ============ P2: combines + location conv (len-skipped, scalar) ===
        if (bid < 64) att_combine(bid*NTHR + tid, par, abih, abhh);
        else if (bid < 128 && t > 0) dec_combine((bid-64)*NTHR + tid, t, dbih, dbhh);

        for (int i=tid; i<8192; i+=NTHR) sX[i] = g_CW2T[i];
        __syncthreads();
        {
            int rep = tid >> 7;
            int d = tid & 127;
            for (int task = lt0 + rep; task < lt1; task += 4) {
                int b = task >> 7, s0 = (task & 127)*4;
                if (s0 >= sLen[b]) continue;          // dead positions: aw==0 beyond len
                float wa[34], wb[34];
#pragma unroll
                for (int j=0; j<34; j++){
                    int sg2 = s0 - 15 + j;
                    bool ok = (sg2 >= 0 && sg2 < NTIN);
                    wa[j] = ok ? g_AW [b*NTIN + sg2] : 0.f;
                    wb[j] = ok ? g_AWC[b*NTIN + sg2] : 0.f;
                }
                float a0=0.f, a1=0.f, a2=0.f, a3=0.f;
#pragma unroll
                for (int k=0; k<31; k++){
                    float w = sX[k*128 + d];
                    a0 += w*wa[k]; a1 += w*wa[k+1]; a2 += w*wa[k+2]; a3 += w*wa[k+3];
                }
#pragma unroll
                for (int k=0; k<31; k++){
                    float w = sX[(32+k)*128 + d];
                    a0 += w*wb[k]; a1 += w*wb[k+1]; a2 += w*wb[k+2]; a3 += w*wb[k+3];
                }
                float* dstL = &g_LOC[((size_t)b*NTIN + s0)*NAD + d];
                dstL[0] = a0; dstL[128] = a1; dstL[256] = a2; dstL[384] = a3;
            }
        }
        gsync(gen);

        // ============ P3: attention (blocks 0..31) | dec GEMV K=2048 =======
        if (bid < 32) {
            const int b = bid;
            const int len = sLen[b];
            for (int i=tid; i<1024; i+=NTHR) sAH[i] = g_ACT[b*NAR + i];   // coalesced
            if (tid < 128) sV[tid] = vW[tid];
            __syncthreads();
            for (int dd = 0; dd < 8; dd++) {
                int d = wid*8 + dd;
                const float* qr = qW + (size_t)d*1024;
                float s = 0.f;
                for (int uu = lane; uu < 1024; uu += 32) s += qr[uu]*sAH[uu];
#pragma unroll
                for (int o=16; o>0; o>>=1) s += __shfl_down_sync(0xffffffffu, s, o);
                if (lane == 0) sQ[d] = s + g_locb2[d];
            }
            __syncthreads();
            // energy for s = tid (only for live positions)
            float en = 0.f;
            if (tid < len) {
                const float4* p4 = (const float4*)(g_PMEM + ((size_t)b*NTIN + tid)*NAD);
                const float4* l4 = (const float4*)(g_LOC  + ((size_t)b*NTIN + tid)*NAD);
                float acc = 0.f;
#pragma unroll 8
                for (int dq = 0; dq < 32; dq++) {
                    float4 p = p4[dq], l = l4[dq];
                    int d = dq*4;
                    acc += sV[d+0]*ftanh(sQ[d+0] + p.x + l.x);
                    acc += sV[d+1]*ftanh(sQ[d+1] + p.y + l.y);
                    acc += sV[d+2]*ftanh(sQ[d+2] + p.z + l.z);
                    acc += sV[d+3]*ftanh(sQ[d+3] + p.w + l.w);
                }
                en = acc;
            }
            // shuffle-based max reduction
            float mval = (tid < len) ? en : -1e30f;
#pragma unroll
            for (int o=16; o>0; o>>=1) mval = fmaxf(mval, __shfl_xor_sync(0xffffffffu, mval, o));
            if (lane == 0) sRed[wid] = mval;
            __syncthreads();
            if (tid < 16) {
                float v = sRed[tid];
#pragma unroll
                for (int o=8; o>0; o>>=1) v = fmaxf(v, __shfl_xor_sync(0xffffu, v, o));
                if (tid == 0) sRed[32] = v;
            }
            __syncthreads();
            float mx = sRed[32];
            float e0 = (tid < len) ? expf(en - mx) : 0.f;
            float sval = e0;
#pragma unroll
            for (int o=16; o>0; o>>=1) sval += __shfl_xor_sync(0xffffffffu, sval, o);
            if (lane == 0) sRed[wid] = sval;
            __syncthreads();
            if (tid < 16) {
                float v = sRed[tid];
#pragma unroll
                for (int o=8; o>0; o>>=1) v += __shfl_xor_sync(0xffffu, v, o);
                if (tid == 0) sRed[33] = v;
            }
            __syncthreads();
            float inv = 1.f/sRed[33];
            float a0 = e0*inv;
            sAWS[tid] = a0;
            g_AW [b*NTIN + tid]  = a0;
            g_AWC[b*NTIN + tid] += a0;
            outp[ALIGN_OFF + ((size_t)b*NT + t)*NTIN + tid] = a0;
            __syncthreads();
            // context: warp-split over s (len-bounded), partials in sX[16][576]
            {
                float4 a40=make_float4(0,0,0,0), a41=a40, a42=a40, a43=a40, a44=a40;
                int sbase = wid*32;
                int send = min(sbase + 32, len);
                for (int s = sbase; s < send; s++){
                    float a = sAWS[s];
                    const float4* m4 = (const float4*)(memory + ((size_t)b*NTIN + s)*NE);
                    float4 v;
                    v = m4[lane];      a40.x+=a*v.x; a40.y+=a*v.y; a40.z+=a*v.z; a40.w+=a*v.w;
                    v = m4[lane+32];   a41.x+=a*v.x; a41.y+=a*v.y; a41.z+=a*v.z; a41.w+=a*v.w;
                    v = m4[lane+64];   a42.x+=a*v.x; a42.y+=a*v.y; a42.z+=a*v.z; a42.w+=a*v.w;
                    v = m4[lane+96];   a43.x+=a*v.x; a43.y+=a*v.y; a43.z+=a*v.z; a43.w+=a*v.w;
                    if (lane < 16){ v = m4[lane+128]; a44.x+=a*v.x; a44.y+=a*v.y; a44.z+=a*v.z; a44.w+=a*v.w; }
                }
                float4* p4 = (float4*)(sX + wid*576);
                p4[lane]     = a40;
                p4[lane+32]  = a41;
                p4[lane+64]  = a42;
                p4[lane+96]  = a43;
                if (lane < 16) p4[lane+128] = a44;
            }
            __syncthreads();
            {
                float s1 = 0.f;
#pragma unroll
                for (int w2=0; w2<16; w2++) s1 += sX[w2*576 + tid];
                g_CTX[((size_t)(t+1)*NE + tid)*32 + b] = s1;
                if (tid < 64){
                    float s2 = 0.f;
#pragma unroll
                    for (int w2=0; w2<16; w2++) s2 += sX[w2*576 + 512 + tid];
                    g_CTX[((size_t)(t+1)*NE + 512 + tid)*32 + b] = s2;
                }
            }
        } else if (bid < 144) {
            int a0 = dkb, a1 = min(dke, 1024);
            if (a1 > a0) copy4(sX + (a0-dkb)*32, g_AC[par^1] + a0*32, (a1-a0)*32, tid);
            int b0 = max(dkb, 1024);
            if (dke > b0) copy4(sX + (b0-dkb)*32, g_DH + ((size_t)t*NDR + (b0-1024))*32, (dke-b0)*32, tid);
            zpad(sX, dke - dkb, dklen8, tid);
            __syncthreads();
            unsigned long long acc[16];
#pragma unroll
            for (int q=0;q<16;q++) acc[q] = 0ull;
            gemv2h(g_WDTh + ((size_t)dg*1312 + (dkb>>1))*1024 + du, sX, dklen8, acc);
            ulonglong2* dst = (ulonglong2*)(g_GPD + ((size_t)(dseg*4 + dg)*1024 + du)*32);
#pragma unroll
            for (int q=0;q<8;q++) dst[q] = make_ulonglong2(acc[2*q], acc[2*q+1]);
        }
        gsync(gen);
    }

    // ---- epilogue: ctx GEMV for step NT-1, then final dec combine ----
    if (bid >= 108) {
        copy4(sX, g_CTX + ((size_t)NT*NE + ckb)*32, (cke-ckb)*32, tid);
        zpad(sX, cke - ckb, cklen8, tid);
        __syncthreads();
        unsigned long long acc[16];
#pragma unroll
        for (int q=0;q<16;q++) acc[q] = 0ull;
        gemv2h(g_WDTh + ((size_t)cg*1312 + 1024 + (ckb>>1))*1024 + cu, sX, cklen8, acc);
        ulonglong2* dst = (ulonglong2*)(g_GPD + ((size_t)((14+cseg)*4 + cg)*1024 + cu)*32);
#pragma unroll
        for (int q=0;q<8;q++) dst[q] = make_ulonglong2(acc[2*q], acc[2*q+1]);
    }
    gsync(gen);
    if (bid >= 64 && bid < 128) dec_combine((bid-64)*NTHR + tid, NT, dbih, dbhh);
}

// ---------------- launch ----------------
extern "C" void kernel_launch(void* const* d_in, const int* in_sizes, int n_in,
                              void* d_out, int out_size)
{
    const float* memory  = (const float*)d_in[0];
    const float* dec_in  = (const float*)d_in[1];
    const float* pW1     = (const float*)d_in[2];
    const float* pW2     = (const float*)d_in[3];
    const float* aWih    = (const float*)d_in[4];
    const float* aWhh    = (const float*)d_in[5];
    const float* abih    = (const float*)d_in[6];
    const float* abhh    = (const float*)d_in[7];
    const float* qW      = (const float*)d_in[8];
    const float* memW    = (const float*)d_in[9];
    const float* convW   = (const float*)d_in[10];
    const float* convb   = (const float*)d_in[11];
    const float* locW    = (const float*)d_in[12];
    const float* vW      = (const float*)d_in[13];
    const float* dWih    = (const float*)d_in[14];
    const float* dWhh    = (const float*)d_in[15];
    const float* dbih    = (const float*)d_in[16];
    const float* dbhh    = (const float*)d_in[17];
    const float* projW   = (const float*)d_in[18];
    const float* projb   = (const float*)d_in[19];
    const float* gateW   = (const float*)d_in[20];
    const float* gateb   = (const float*)d_in[21];
    const int*   mlen    = (const int*)  d_in[22];
    float* outp = (float*)d_out;

    prep_k<<<dim3(82,32,8), dim3(32,8)>>>(aWih, aWhh, dWih, dWhh, locW, convW, convb); // 0
    gemm0_k<<<dim3(2,NT),128>>>(pW1, dec_in);                                          // 1
    gemm12_k<<<dim3(2,512,2),128>>>(pW2, memW, memory);                                // 2
    decoder_persist<<<148,NTHR>>>(abih, abhh, dbih, dbhh, qW, vW, memory, mlen, outp); // 3
    gemm5_k<<<dim3(1,NT),128>>>(projW, gateW, projb, gateb, outp);                     // 4
}